// round 8
// baseline (speedup 1.0000x reference)
#include <cuda_runtime.h>

#define NN   50000
#define NDIM 128
#define EDIM 32
#define HDIM 256
#define TE   64
#define TN   64
#define LDA  72   // padded leading dim, keeps 16B alignment for float4 LDS

// scratch: m_i aggregation [N, HD]
__device__ __align__(16) float g_magg[(size_t)NN * HDIM];
// 1 if edge_index buffer is int64 (little-endian pairs), 0 if int32
__device__ int g_idx64;

__device__ __forceinline__ float silu_f(float v) {
    return __fdividef(v, 1.0f + __expf(-v));
}

// index accessors: ei32 = edge_index viewed as int32. row i, col i.
__device__ __forceinline__ int load_row(const int* __restrict__ ei32, long long i,
                                        long long E, int idx64) {
    int r = idx64 ? ei32[2*i] : ei32[i];
    return (r < 0) ? 0 : (r >= NN ? NN - 1 : r);
}
__device__ __forceinline__ int load_col(const int* __restrict__ ei32, long long i,
                                        long long E, int idx64) {
    int c = idx64 ? ei32[2*(E + i)] : ei32[E + i];
    return (c < 0) ? 0 : (c >= NN ? NN - 1 : c);
}

// ---------- tile GEMM core: 8 edges x 4 cols per thread, K-major smem A ----------
// sA: [K][LDA] (edge-minor, shared), W: [K][HDIM] row-major (global).
template<int K>
__device__ __forceinline__ void mm_body(const float* sA,
                                        const float* __restrict__ W,
                                        int e0, int c0, float acc[32])
{
    const float* ap = sA + e0;
    const float* wp = W + c0;
    #pragma unroll 4
    for (int k = 0; k < K; k++) {
        float4 a0 = *reinterpret_cast<const float4*>(ap);
        float4 a1 = *reinterpret_cast<const float4*>(ap + 4);
        float4 w  = *reinterpret_cast<const float4*>(wp);
        float a[8] = { a0.x, a0.y, a0.z, a0.w, a1.x, a1.y, a1.z, a1.w };
        #pragma unroll
        for (int ee = 0; ee < 8; ee++) {
            acc[ee*4+0] = fmaf(a[ee], w.x, acc[ee*4+0]);
            acc[ee*4+1] = fmaf(a[ee], w.y, acc[ee*4+1]);
            acc[ee*4+2] = fmaf(a[ee], w.z, acc[ee*4+2]);
            acc[ee*4+3] = fmaf(a[ee], w.w, acc[ee*4+3]);
        }
        ap += LDA; wp += HDIM;
    }
}

// ---------- init: dtype probe, zero m_agg, x_out = x ----------
__global__ void init_kernel(const float* __restrict__ x, float* __restrict__ xout,
                            const int* __restrict__ ei32) {
    long long i = (long long)blockIdx.x * blockDim.x + threadIdx.x;
    if (i == 0) {
        // int64 little-endian values < 2^31 have zero high words
        int all_hi_zero = 1;
        for (int q = 0; q < 64; q++)
            if (ei32[2*q + 1] != 0) { all_hi_zero = 0; break; }
        g_idx64 = all_hi_zero;
    }
    if (i < (long long)NN * HDIM) g_magg[i] = 0.0f;
    if (i < (long long)NN * 3)    xout[i] = x[i];
}

// ---------- fused edge pipeline ----------
__global__ __launch_bounds__(512, 1)
void edge_kernel(const float* __restrict__ h, const float* __restrict__ x,
                 const int* __restrict__ ei32, const float* __restrict__ ea,
                 const float* __restrict__ mW1, const float* __restrict__ mb1,
                 const float* __restrict__ mW2, const float* __restrict__ mb2,
                 const float* __restrict__ cW1, const float* __restrict__ cb1,
                 const float* __restrict__ cW2,
                 float* __restrict__ xout, long long E)
{
    extern __shared__ float sm[];
    float* s_a    = sm;                      // 289*LDA (edge_in, later m2)
    float* s_b    = sm + 289 * LDA;          // 256*LDA (m1)
    float* s_part = s_b + 256 * LDA;         // 16*8 per-warp coef partials
    float* s_dx   = s_part + 16 * 8;         // 192
    int*   s_row  = (int*)(s_dx + TE * 3);   // 64

    const int idx64 = g_idx64;
    long long base = (long long)blockIdx.x * TE;
    int tid = threadIdx.x;
    int lane = tid & 31, warp = tid >> 5;

    // --- Phase A: build edge_in [289][64] in smem ---
    if (tid < TE) {
        long long ge = base + tid;
        int e = tid;
        if (ge < E) {
            int r = load_row(ei32, ge, E, idx64);
            int c = load_col(ei32, ge, E, idx64);
            s_row[e] = r;
            float d0 = x[r*3+0] - x[c*3+0];
            float d1 = x[r*3+1] - x[c*3+1];
            float d2 = x[r*3+2] - x[c*3+2];
            s_dx[e*3+0] = d0; s_dx[e*3+1] = d1; s_dx[e*3+2] = d2;
            s_a[256*LDA + e] = d0*d0 + d1*d1 + d2*d2 + 1e-8f;
        } else {
            s_row[e] = -1;
            s_dx[e*3+0] = 0.f; s_dx[e*3+1] = 0.f; s_dx[e*3+2] = 0.f;
            s_a[256*LDA + e] = 0.f;
        }
    }
    // h[row], h[col] gather: 16 warps x 4 edges, one float4 per lane
    #pragma unroll
    for (int q = 0; q < 4; q++) {
        int e = warp*4 + q;
        long long ge = base + e; if (ge >= E) ge = E - 1;
        int r = load_row(ei32, ge, E, idx64);
        int c = load_col(ei32, ge, E, idx64);
        float4 hr = reinterpret_cast<const float4*>(h)[(size_t)r*(NDIM/4) + lane];
        float4 hc = reinterpret_cast<const float4*>(h)[(size_t)c*(NDIM/4) + lane];
        int k = lane * 4;
        s_a[(k+0)*LDA+e] = hr.x; s_a[(k+1)*LDA+e] = hr.y;
        s_a[(k+2)*LDA+e] = hr.z; s_a[(k+3)*LDA+e] = hr.w;
        s_a[(NDIM+k+0)*LDA+e] = hc.x; s_a[(NDIM+k+1)*LDA+e] = hc.y;
        s_a[(NDIM+k+2)*LDA+e] = hc.z; s_a[(NDIM+k+3)*LDA+e] = hc.w;
    }
    // edge_attr: 512 threads -> e=tid/8, quad=tid%8
    {
        int e = tid >> 3, q = tid & 7;
        long long ge = base + e; if (ge >= E) ge = E - 1;
        float4 a = reinterpret_cast<const float4*>(ea)[ge*(EDIM/4) + q];
        int k = 257 + q*4;
        s_a[(k+0)*LDA+e] = a.x; s_a[(k+1)*LDA+e] = a.y;
        s_a[(k+2)*LDA+e] = a.z; s_a[(k+3)*LDA+e] = a.w;
    }
    __syncthreads();

    int eg = tid >> 6;          // 0..7  edge group (8 edges)
    int cg = tid & 63;          // 0..63 col group (4 cols)
    int e0 = eg * 8;
    int c0 = cg * 4;

    float acc[32];

    // --- GEMM1: m1 = silu(edge_in @ mW1 + mb1), K=289 ---
    #pragma unroll
    for (int i = 0; i < 32; i++) acc[i] = 0.f;
    mm_body<2*NDIM + 1 + EDIM>(s_a, mW1, e0, c0, acc);
    {
        float bb[4] = { mb1[c0], mb1[c0+1], mb1[c0+2], mb1[c0+3] };
        #pragma unroll
        for (int ee = 0; ee < 8; ee++) {
            int e = e0 + ee;
            #pragma unroll
            for (int j = 0; j < 4; j++)
                s_b[(c0+j)*LDA + e] = silu_f(acc[ee*4+j] + bb[j]);
        }
    }
    __syncthreads();

    // --- GEMM2: m2 = silu(m1 @ mW2 + mb2), K=256; store to s_a + aggregate m_i ---
    #pragma unroll
    for (int i = 0; i < 32; i++) acc[i] = 0.f;
    mm_body<HDIM>(s_b, mW2, e0, c0, acc);
    {
        float bb[4] = { mb2[c0], mb2[c0+1], mb2[c0+2], mb2[c0+3] };
        #pragma unroll
        for (int ee = 0; ee < 8; ee++) {
            int e = e0 + ee;
            int r = s_row[e];
            #pragma unroll
            for (int j = 0; j < 4; j++) {
                float v = silu_f(acc[ee*4+j] + bb[j]);
                s_a[(c0+j)*LDA + e] = v;
                if (r >= 0) atomicAdd(&g_magg[(size_t)r*HDIM + c0 + j], v);
            }
        }
    }
    __syncthreads();

    // --- GEMM3: c1 = silu(m2 @ cW1 + cb1); coef = c1 @ cW2 (shuffle-reduced) ---
    #pragma unroll
    for (int i = 0; i < 32; i++) acc[i] = 0.f;
    mm_body<HDIM>(s_a, cW1, e0, c0, acc);
    {
        float bb[4] = { cb1[c0], cb1[c0+1], cb1[c0+2], cb1[c0+3] };
        float wv[4] = { cW2[c0], cW2[c0+1], cW2[c0+2], cW2[c0+3] };
        float pe[8];
        #pragma unroll
        for (int ee = 0; ee < 8; ee++) {
            float s = 0.f;
            #pragma unroll
            for (int j = 0; j < 4; j++)
                s += silu_f(acc[ee*4+j] + bb[j]) * wv[j];
            pe[ee] = s;
        }
        // butterfly reduce across the 32 lanes of this warp (all share edges e0..e0+7)
        #pragma unroll
        for (int o = 16; o > 0; o >>= 1) {
            #pragma unroll
            for (int q = 0; q < 8; q++)
                pe[q] += __shfl_xor_sync(0xffffffffu, pe[q], o);
        }
        if (lane == 0) {
            #pragma unroll
            for (int q = 0; q < 8; q++) s_part[warp*8 + q] = pe[q];
        }
    }
    __syncthreads();

    // --- x aggregation: coef[e] = s_part[2*eg][q] + s_part[2*eg+1][q] ---
    if (tid < TE) {
        int e = tid; int r = s_row[e];
        if (r >= 0) {
            int egg = e >> 3, q = e & 7;
            float cf = s_part[egg*16 + q] + s_part[egg*16 + 8 + q];
            atomicAdd(&xout[r*3+0], cf * s_dx[e*3+0]);
            atomicAdd(&xout[r*3+1], cf * s_dx[e*3+1]);
            atomicAdd(&xout[r*3+2], cf * s_dx[e*3+2]);
        }
    }
}

// ---------- fused node MLP + residual + LayerNorm ----------
__global__ __launch_bounds__(512, 1)
void node_kernel(const float* __restrict__ h,
                 const float* __restrict__ nW1, const float* __restrict__ nb1,
                 const float* __restrict__ nW2, const float* __restrict__ nb2,
                 const float* __restrict__ gamma, const float* __restrict__ beta,
                 float* __restrict__ hout)
{
    extern __shared__ float sm[];
    float* s_a   = sm;                    // 384*LDA  (h_in; rows<128 = h, kept for residual)
    float* s_b   = sm + 384 * LDA;        // 256*LDA  (t)
    float* s_res = s_a + NDIM * LDA;      // overlay onto s_a rows >= 128 (64*128 floats)

    int tid = threadIdx.x, lane = tid & 31, warp = tid >> 5;
    int n0 = blockIdx.x * TN;

    // load h_in = [h(128) ; m_agg(256)] K-major
    #pragma unroll
    for (int q = 0; q < 4; q++) {
        int e = warp*4 + q;
        int n = n0 + e; if (n >= NN) n = NN - 1;
        float4 hv = reinterpret_cast<const float4*>(h)[(size_t)n*(NDIM/4) + lane];
        int k = lane * 4;
        s_a[(k+0)*LDA+e] = hv.x; s_a[(k+1)*LDA+e] = hv.y;
        s_a[(k+2)*LDA+e] = hv.z; s_a[(k+3)*LDA+e] = hv.w;
        float4 m0 = reinterpret_cast<const float4*>(g_magg)[(size_t)n*(HDIM/4) + lane];
        float4 m1 = reinterpret_cast<const float4*>(g_magg)[(size_t)n*(HDIM/4) + lane + 32];
        int k0 = NDIM + lane*4;
        s_a[(k0+0)*LDA+e] = m0.x; s_a[(k0+1)*LDA+e] = m0.y;
        s_a[(k0+2)*LDA+e] = m0.z; s_a[(k0+3)*LDA+e] = m0.w;
        int k1 = NDIM + 128 + lane*4;
        s_a[(k1+0)*LDA+e] = m1.x; s_a[(k1+1)*LDA+e] = m1.y;
        s_a[(k1+2)*LDA+e] = m1.z; s_a[(k1+3)*LDA+e] = m1.w;
    }
    __syncthreads();

    int eg = tid >> 6, cg = tid & 63;
    int e0 = eg * 8, c0 = cg * 4;

    // GEMM1: t = silu(h_in @ nW1 + nb1), K=384, 256 cols
    float acc[32];
    #pragma unroll
    for (int i = 0; i < 32; i++) acc[i] = 0.f;
    mm_body<NDIM + HDIM>(s_a, nW1, e0, c0, acc);
    {
        float bb[4] = { nb1[c0], nb1[c0+1], nb1[c0+2], nb1[c0+3] };
        #pragma unroll
        for (int ee = 0; ee < 8; ee++) {
            int e = e0 + ee;
            #pragma unroll
            for (int j = 0; j < 4; j++)
                s_b[(c0+j)*LDA + e] = silu_f(acc[ee*4+j] + bb[j]);
        }
    }
    __syncthreads();

    // GEMM2: h_res = h + t @ nW2 + nb2 ; K=256, 128 cols (2 cols/thread)
    {
        int c20 = cg * 2;
        float a2[16];
        #pragma unroll
        for (int i = 0; i < 16; i++) a2[i] = 0.f;
        const float* ap = s_b + e0;
        const float* wp = nW2 + c20;
        #pragma unroll 4
        for (int k = 0; k < HDIM; k++) {
            float4 b0 = *reinterpret_cast<const float4*>(ap);
            float4 b1 = *reinterpret_cast<const float4*>(ap + 4);
            float2 w  = *reinterpret_cast<const float2*>(wp);
            float a[8] = { b0.x, b0.y, b0.z, b0.w, b1.x, b1.y, b1.z, b1.w };
            #pragma unroll
            for (int ee = 0; ee < 8; ee++) {
                a2[ee*2+0] = fmaf(a[ee], w.x, a2[ee*2+0]);
                a2[ee*2+1] = fmaf(a[ee], w.y, a2[ee*2+1]);
            }
            ap += LDA; wp += NDIM;
        }
        float bz0 = nb2[c20], bz1 = nb2[c20+1];
        #pragma unroll
        for (int ee = 0; ee < 8; ee++) {
            int e = e0 + ee;
            s_res[e*NDIM + c20]   = s_a[c20*LDA + e]     + a2[ee*2+0] + bz0;
            s_res[e*NDIM + c20+1] = s_a[(c20+1)*LDA + e] + a2[ee*2+1] + bz1;
        }
    }
    __syncthreads();

    // LayerNorm per node (warp per 4 nodes, 1 float4 per lane)
    #pragma unroll
    for (int q = 0; q < 4; q++) {
        int e = warp*4 + q;
        int n = n0 + e;
        float4 v = reinterpret_cast<const float4*>(s_res + e*NDIM)[lane];
        float s  = v.x + v.y + v.z + v.w;
        float sq = v.x*v.x + v.y*v.y + v.z*v.z + v.w*v.w;
        #pragma unroll
        for (int o = 16; o > 0; o >>= 1) {
            s  += __shfl_xor_sync(0xffffffffu, s,  o);
            sq += __shfl_xor_sync(0xffffffffu, sq, o);
        }
        float mu   = s * (1.0f / NDIM);
        float var  = sq * (1.0f / NDIM) - mu * mu;
        float rstd = rsqrtf(var + 1e-5f);
        if (n < NN) {
            float4 g  = reinterpret_cast<const float4*>(gamma)[lane];
            float4 be = reinterpret_cast<const float4*>(beta)[lane];
            float4 o;
            o.x = (v.x - mu) * rstd * g.x + be.x;
            o.y = (v.y - mu) * rstd * g.y + be.y;
            o.z = (v.z - mu) * rstd * g.z + be.z;
            o.w = (v.w - mu) * rstd * g.w + be.w;
            reinterpret_cast<float4*>(hout + (size_t)n * NDIM)[lane] = o;
        }
    }
}

extern "C" void kernel_launch(void* const* d_in, const int* in_sizes, int n_in,
                              void* d_out, int out_size)
{
    const float* h   = (const float*)d_in[0];
    const float* x   = (const float*)d_in[1];
    const int*   ei32 = (const int*)d_in[2];     // int32 OR int64 (probed at runtime)
    const float* ea  = (const float*)d_in[3];
    const float* mW1 = (const float*)d_in[4];
    const float* mb1 = (const float*)d_in[5];
    const float* mW2 = (const float*)d_in[6];
    const float* mb2 = (const float*)d_in[7];
    const float* nW1 = (const float*)d_in[8];
    const float* nb1 = (const float*)d_in[9];
    const float* nW2 = (const float*)d_in[10];
    const float* nb2 = (const float*)d_in[11];
    const float* cW1 = (const float*)d_in[12];
    const float* cb1 = (const float*)d_in[13];
    const float* cW2 = (const float*)d_in[14];
    const float* gamma = (const float*)d_in[15];
    const float* beta  = (const float*)d_in[16];

    float* hout = (float*)d_out;
    float* xout = hout + (size_t)NN * NDIM;
    long long E = (long long)in_sizes[2] / 2;    // element count / 2, dtype-independent

    const int edge_smem = (289*LDA + 256*LDA + 16*8 + TE*3 + TE) * 4;   // ~158.5 KB
    const int node_smem = ((NDIM+HDIM)*LDA + HDIM*LDA) * 4;             // ~184 KB
    cudaFuncSetAttribute(edge_kernel, cudaFuncAttributeMaxDynamicSharedMemorySize, edge_smem);
    cudaFuncSetAttribute(node_kernel, cudaFuncAttributeMaxDynamicSharedMemorySize, node_smem);

    {
        long long tot = (long long)NN * HDIM;
        int blocks = (int)((tot + 511) / 512);
        init_kernel<<<blocks, 512>>>(x, xout, ei32);
    }
    {
        int blocks = (int)((E + TE - 1) / TE);
        edge_kernel<<<blocks, 512, edge_smem>>>(h, x, ei32, ea, mW1, mb1, mW2, mb2,
                                                cW1, cb1, cW2, xout, E);
    }
    {
        int blocks = (NN + TN - 1) / TN;
        node_kernel<<<blocks, 512, node_smem>>>(h, nW1, nb1, nW2, nb2, gamma, beta, hout);
    }
}

// round 9
// speedup vs baseline: 1.1160x; 1.1160x over previous
#include <cuda_runtime.h>

#define NN   50000
#define NDIM 128
#define EDIM 32
#define HDIM 256
#define TE   64
#define TN   64
#define LDA  72   // padded leading dim, keeps 16B alignment for vector LDS

// scratch: m_i aggregation [N, HD]
__device__ __align__(16) float g_magg[(size_t)NN * HDIM];
// 1 if edge_index buffer is int64 (little-endian pairs), 0 if int32
__device__ int g_idx64;

// ---------- packed f32x2 helpers (B300 FFMA2: 2 fp32 FMAs per issue) ----------
__device__ __forceinline__ unsigned long long pack2f(float lo, float hi) {
    unsigned long long r;
    asm("mov.b64 %0, {%1, %2};" : "=l"(r)
        : "r"(__float_as_uint(lo)), "r"(__float_as_uint(hi)));
    return r;
}
__device__ __forceinline__ void unpack2f(unsigned long long v, float& lo, float& hi) {
    unsigned int a, b;
    asm("mov.b64 {%0, %1}, %2;" : "=r"(a), "=r"(b) : "l"(v));
    lo = __uint_as_float(a); hi = __uint_as_float(b);
}
__device__ __forceinline__ void fma2(unsigned long long& d, unsigned long long a,
                                     unsigned long long b) {
    asm("fma.rn.f32x2 %0, %1, %2, %0;" : "+l"(d) : "l"(a), "l"(b));
}
__device__ __forceinline__ float silu_f(float v) {
    return __fdividef(v, 1.0f + __expf(-v));
}

// index accessors: ei32 = edge_index viewed as int32 (dtype probed at runtime)
__device__ __forceinline__ int load_row(const int* __restrict__ ei32, long long i,
                                        long long E, int idx64) {
    int r = idx64 ? ei32[2*i] : ei32[i];
    return (r < 0) ? 0 : (r >= NN ? NN - 1 : r);
}
__device__ __forceinline__ int load_col(const int* __restrict__ ei32, long long i,
                                        long long E, int idx64) {
    int c = idx64 ? ei32[2*(E + i)] : ei32[E + i];
    return (c < 0) ? 0 : (c >= NN ? NN - 1 : c);
}

// ---------- tile GEMM core: 8 edges (4 pairs) x 4 cols per thread ----------
// sA: [K][LDA] K-major shared, W: [K][HDIM] row-major global.
// acc[p*4+j]: packed pair of edges (e0+2p, e0+2p+1), col c0+j.
template<int K>
__device__ __forceinline__ void mm_body(const float* sA,
                                        const float* __restrict__ W,
                                        int e0, int c0,
                                        unsigned long long acc[16])
{
    const float* ap = sA + e0;
    const float* wp = W + c0;
    #pragma unroll 4
    for (int k = 0; k < K; k++) {
        ulonglong2 a01 = *reinterpret_cast<const ulonglong2*>(ap);
        ulonglong2 a23 = *reinterpret_cast<const ulonglong2*>(ap + 4);
        float4 w = *reinterpret_cast<const float4*>(wp);
        unsigned long long w0 = pack2f(w.x, w.x);
        unsigned long long w1 = pack2f(w.y, w.y);
        unsigned long long w2 = pack2f(w.z, w.z);
        unsigned long long w3 = pack2f(w.w, w.w);
        fma2(acc[0],  a01.x, w0); fma2(acc[1],  a01.x, w1);
        fma2(acc[2],  a01.x, w2); fma2(acc[3],  a01.x, w3);
        fma2(acc[4],  a01.y, w0); fma2(acc[5],  a01.y, w1);
        fma2(acc[6],  a01.y, w2); fma2(acc[7],  a01.y, w3);
        fma2(acc[8],  a23.x, w0); fma2(acc[9],  a23.x, w1);
        fma2(acc[10], a23.x, w2); fma2(acc[11], a23.x, w3);
        fma2(acc[12], a23.y, w0); fma2(acc[13], a23.y, w1);
        fma2(acc[14], a23.y, w2); fma2(acc[15], a23.y, w3);
        ap += LDA; wp += HDIM;
    }
}

// ---------- init: dtype probe, zero m_agg, x_out = x ----------
__global__ void init_kernel(const float* __restrict__ x, float* __restrict__ xout,
                            const int* __restrict__ ei32) {
    long long i = (long long)blockIdx.x * blockDim.x + threadIdx.x;
    if (i == 0) {
        int all_hi_zero = 1;
        for (int q = 0; q < 64; q++)
            if (ei32[2*q + 1] != 0) { all_hi_zero = 0; break; }
        g_idx64 = all_hi_zero;
    }
    if (i < (long long)NN * HDIM) g_magg[i] = 0.0f;
    if (i < (long long)NN * 3)    xout[i] = x[i];
}

// ---------- fused edge pipeline ----------
__global__ __launch_bounds__(512, 1)
void edge_kernel(const float* __restrict__ h, const float* __restrict__ x,
                 const int* __restrict__ ei32, const float* __restrict__ ea,
                 const float* __restrict__ mW1, const float* __restrict__ mb1,
                 const float* __restrict__ mW2, const float* __restrict__ mb2,
                 const float* __restrict__ cW1, const float* __restrict__ cb1,
                 const float* __restrict__ cW2,
                 float* __restrict__ xout, long long E)
{
    extern __shared__ float sm[];
    float* s_a    = sm;                      // 289*LDA (edge_in, later m2)
    float* s_b    = sm + 289 * LDA;          // 256*LDA (m1)
    float* s_part = s_b + 256 * LDA;         // 16*8 per-warp coef partials
    float* s_dx   = s_part + 16 * 8;         // 192
    int*   s_row  = (int*)(s_dx + TE * 3);   // 64

    const int idx64 = g_idx64;
    long long base = (long long)blockIdx.x * TE;
    int tid = threadIdx.x;
    int lane = tid & 31, warp = tid >> 5;

    // --- Phase A: build edge_in [289][64] in smem ---
    if (tid < TE) {
        long long ge = base + tid;
        int e = tid;
        if (ge < E) {
            int r = load_row(ei32, ge, E, idx64);
            int c = load_col(ei32, ge, E, idx64);
            s_row[e] = r;
            float d0 = x[r*3+0] - x[c*3+0];
            float d1 = x[r*3+1] - x[c*3+1];
            float d2 = x[r*3+2] - x[c*3+2];
            s_dx[e*3+0] = d0; s_dx[e*3+1] = d1; s_dx[e*3+2] = d2;
            s_a[256*LDA + e] = d0*d0 + d1*d1 + d2*d2 + 1e-8f;
        } else {
            s_row[e] = -1;
            s_dx[e*3+0] = 0.f; s_dx[e*3+1] = 0.f; s_dx[e*3+2] = 0.f;
            s_a[256*LDA + e] = 0.f;
        }
    }
    // h[row], h[col] gather: 16 warps x 4 edges, one float4 per lane
    #pragma unroll
    for (int q = 0; q < 4; q++) {
        int e = warp*4 + q;
        long long ge = base + e; if (ge >= E) ge = E - 1;
        int r = load_row(ei32, ge, E, idx64);
        int c = load_col(ei32, ge, E, idx64);
        float4 hr = reinterpret_cast<const float4*>(h)[(size_t)r*(NDIM/4) + lane];
        float4 hc = reinterpret_cast<const float4*>(h)[(size_t)c*(NDIM/4) + lane];
        int k = lane * 4;
        s_a[(k+0)*LDA+e] = hr.x; s_a[(k+1)*LDA+e] = hr.y;
        s_a[(k+2)*LDA+e] = hr.z; s_a[(k+3)*LDA+e] = hr.w;
        s_a[(NDIM+k+0)*LDA+e] = hc.x; s_a[(NDIM+k+1)*LDA+e] = hc.y;
        s_a[(NDIM+k+2)*LDA+e] = hc.z; s_a[(NDIM+k+3)*LDA+e] = hc.w;
    }
    // edge_attr: 512 threads -> e=tid/8, quad=tid%8
    {
        int e = tid >> 3, q = tid & 7;
        long long ge = base + e; if (ge >= E) ge = E - 1;
        float4 a = reinterpret_cast<const float4*>(ea)[ge*(EDIM/4) + q];
        int k = 257 + q*4;
        s_a[(k+0)*LDA+e] = a.x; s_a[(k+1)*LDA+e] = a.y;
        s_a[(k+2)*LDA+e] = a.z; s_a[(k+3)*LDA+e] = a.w;
    }
    __syncthreads();

    int eg = tid >> 6;          // 0..7  edge group (8 edges)
    int cg = tid & 63;          // 0..63 col group (4 cols)
    int e0 = eg * 8;
    int c0 = cg * 4;

    unsigned long long acc[16];

    // --- GEMM1: m1 = silu(edge_in @ mW1 + mb1), K=289 ---
    #pragma unroll
    for (int i = 0; i < 16; i++) acc[i] = 0ull;
    mm_body<2*NDIM + 1 + EDIM>(s_a, mW1, e0, c0, acc);
    {
        float bb[4] = { mb1[c0], mb1[c0+1], mb1[c0+2], mb1[c0+3] };
        #pragma unroll
        for (int p = 0; p < 4; p++) {
            int e = e0 + 2*p;
            #pragma unroll
            for (int j = 0; j < 4; j++) {
                float lo, hi; unpack2f(acc[p*4+j], lo, hi);
                s_b[(c0+j)*LDA + e]     = silu_f(lo + bb[j]);
                s_b[(c0+j)*LDA + e + 1] = silu_f(hi + bb[j]);
            }
        }
    }
    __syncthreads();

    // --- GEMM2: m2 = silu(m1 @ mW2 + mb2), K=256; store to s_a + aggregate m_i ---
    #pragma unroll
    for (int i = 0; i < 16; i++) acc[i] = 0ull;
    mm_body<HDIM>(s_b, mW2, e0, c0, acc);
    {
        float bb[4] = { mb2[c0], mb2[c0+1], mb2[c0+2], mb2[c0+3] };
        #pragma unroll
        for (int p = 0; p < 4; p++) {
            int e = e0 + 2*p;
            int r0 = s_row[e], r1 = s_row[e+1];
            #pragma unroll
            for (int j = 0; j < 4; j++) {
                float lo, hi; unpack2f(acc[p*4+j], lo, hi);
                float v0 = silu_f(lo + bb[j]);
                float v1 = silu_f(hi + bb[j]);
                s_a[(c0+j)*LDA + e]     = v0;
                s_a[(c0+j)*LDA + e + 1] = v1;
                if (r0 >= 0) atomicAdd(&g_magg[(size_t)r0*HDIM + c0 + j], v0);
                if (r1 >= 0) atomicAdd(&g_magg[(size_t)r1*HDIM + c0 + j], v1);
            }
        }
    }
    __syncthreads();

    // --- GEMM3: c1 = silu(m2 @ cW1 + cb1); coef = c1 @ cW2 (shuffle-reduced) ---
    #pragma unroll
    for (int i = 0; i < 16; i++) acc[i] = 0ull;
    mm_body<HDIM>(s_a, cW1, e0, c0, acc);
    {
        float bb[4] = { cb1[c0], cb1[c0+1], cb1[c0+2], cb1[c0+3] };
        float wv[4] = { cW2[c0], cW2[c0+1], cW2[c0+2], cW2[c0+3] };
        float pe[8];
        #pragma unroll
        for (int q = 0; q < 8; q++) pe[q] = 0.f;
        #pragma unroll
        for (int p = 0; p < 4; p++) {
            #pragma unroll
            for (int j = 0; j < 4; j++) {
                float lo, hi; unpack2f(acc[p*4+j], lo, hi);
                pe[2*p]   += silu_f(lo + bb[j]) * wv[j];
                pe[2*p+1] += silu_f(hi + bb[j]) * wv[j];
            }
        }
        // butterfly reduce across the 32 lanes of this warp (all share edges e0..e0+7)
        #pragma unroll
        for (int o = 16; o > 0; o >>= 1) {
            #pragma unroll
            for (int q = 0; q < 8; q++)
                pe[q] += __shfl_xor_sync(0xffffffffu, pe[q], o);
        }
        if (lane == 0) {
            #pragma unroll
            for (int q = 0; q < 8; q++) s_part[warp*8 + q] = pe[q];
        }
    }
    __syncthreads();

    // --- x aggregation: coef[e] = s_part[2*eg][q] + s_part[2*eg+1][q] ---
    if (tid < TE) {
        int e = tid; int r = s_row[e];
        if (r >= 0) {
            int egg = e >> 3, q = e & 7;
            float cf = s_part[egg*16 + q] + s_part[egg*16 + 8 + q];
            atomicAdd(&xout[r*3+0], cf * s_dx[e*3+0]);
            atomicAdd(&xout[r*3+1], cf * s_dx[e*3+1]);
            atomicAdd(&xout[r*3+2], cf * s_dx[e*3+2]);
        }
    }
}

// ---------- fused node MLP + residual + LayerNorm ----------
__global__ __launch_bounds__(512, 1)
void node_kernel(const float* __restrict__ h,
                 const float* __restrict__ nW1, const float* __restrict__ nb1,
                 const float* __restrict__ nW2, const float* __restrict__ nb2,
                 const float* __restrict__ gamma, const float* __restrict__ beta,
                 float* __restrict__ hout)
{
    extern __shared__ float sm[];
    float* s_a   = sm;                    // 384*LDA  (h_in; rows<128 = h, kept for residual)
    float* s_b   = sm + 384 * LDA;        // 256*LDA  (t)
    float* s_res = s_a + NDIM * LDA;      // overlay onto s_a rows >= 128 (64*128 floats)

    int tid = threadIdx.x, lane = tid & 31, warp = tid >> 5;
    int n0 = blockIdx.x * TN;

    // load h_in = [h(128) ; m_agg(256)] K-major
    #pragma unroll
    for (int q = 0; q < 4; q++) {
        int e = warp*4 + q;
        int n = n0 + e; if (n >= NN) n = NN - 1;
        float4 hv = reinterpret_cast<const float4*>(h)[(size_t)n*(NDIM/4) + lane];
        int k = lane * 4;
        s_a[(k+0)*LDA+e] = hv.x; s_a[(k+1)*LDA+e] = hv.y;
        s_a[(k+2)*LDA+e] = hv.z; s_a[(k+3)*LDA+e] = hv.w;
        float4 m0 = reinterpret_cast<const float4*>(g_magg)[(size_t)n*(HDIM/4) + lane];
        float4 m1 = reinterpret_cast<const float4*>(g_magg)[(size_t)n*(HDIM/4) + lane + 32];
        int k0 = NDIM + lane*4;
        s_a[(k0+0)*LDA+e] = m0.x; s_a[(k0+1)*LDA+e] = m0.y;
        s_a[(k0+2)*LDA+e] = m0.z; s_a[(k0+3)*LDA+e] = m0.w;
        int k1 = NDIM + 128 + lane*4;
        s_a[(k1+0)*LDA+e] = m1.x; s_a[(k1+1)*LDA+e] = m1.y;
        s_a[(k1+2)*LDA+e] = m1.z; s_a[(k1+3)*LDA+e] = m1.w;
    }
    __syncthreads();

    int eg = tid >> 6, cg = tid & 63;
    int e0 = eg * 8, c0 = cg * 4;

    // GEMM1: t = silu(h_in @ nW1 + nb1), K=384, 256 cols
    unsigned long long acc[16];
    #pragma unroll
    for (int i = 0; i < 16; i++) acc[i] = 0ull;
    mm_body<NDIM + HDIM>(s_a, nW1, e0, c0, acc);
    {
        float bb[4] = { nb1[c0], nb1[c0+1], nb1[c0+2], nb1[c0+3] };
        #pragma unroll
        for (int p = 0; p < 4; p++) {
            int e = e0 + 2*p;
            #pragma unroll
            for (int j = 0; j < 4; j++) {
                float lo, hi; unpack2f(acc[p*4+j], lo, hi);
                s_b[(c0+j)*LDA + e]     = silu_f(lo + bb[j]);
                s_b[(c0+j)*LDA + e + 1] = silu_f(hi + bb[j]);
            }
        }
    }
    __syncthreads();

    // GEMM2: h_res = h + t @ nW2 + nb2 ; K=256, 128 cols (2 cols/thread)
    {
        int c20 = cg * 2;
        unsigned long long a2[8];
        #pragma unroll
        for (int i = 0; i < 8; i++) a2[i] = 0ull;
        const float* ap = s_b + e0;
        const float* wp = nW2 + c20;
        #pragma unroll 4
        for (int k = 0; k < HDIM; k++) {
            ulonglong2 a01 = *reinterpret_cast<const ulonglong2*>(ap);
            ulonglong2 a23 = *reinterpret_cast<const ulonglong2*>(ap + 4);
            float2 w = *reinterpret_cast<const float2*>(wp);
            unsigned long long w0 = pack2f(w.x, w.x);
            unsigned long long w1 = pack2f(w.y, w.y);
            fma2(a2[0], a01.x, w0); fma2(a2[1], a01.x, w1);
            fma2(a2[2], a01.y, w0); fma2(a2[3], a01.y, w1);
            fma2(a2[4], a23.x, w0); fma2(a2[5], a23.x, w1);
            fma2(a2[6], a23.y, w0); fma2(a2[7], a23.y, w1);
            ap += LDA; wp += NDIM;
        }
        float bz0 = nb2[c20], bz1 = nb2[c20+1];
        #pragma unroll
        for (int p = 0; p < 4; p++) {
            int e = e0 + 2*p;
            float lo, hi;
            unpack2f(a2[p*2+0], lo, hi);
            s_res[e*NDIM + c20]       = s_a[c20*LDA + e]       + lo + bz0;
            s_res[(e+1)*NDIM + c20]   = s_a[c20*LDA + e + 1]   + hi + bz0;
            unpack2f(a2[p*2+1], lo, hi);
            s_res[e*NDIM + c20+1]     = s_a[(c20+1)*LDA + e]     + lo + bz1;
            s_res[(e+1)*NDIM + c20+1] = s_a[(c20+1)*LDA + e + 1] + hi + bz1;
        }
    }
    __syncthreads();

    // LayerNorm per node (warp per 4 nodes, 1 float4 per lane)
    #pragma unroll
    for (int q = 0; q < 4; q++) {
        int e = warp*4 + q;
        int n = n0 + e;
        float4 v = reinterpret_cast<const float4*>(s_res + e*NDIM)[lane];
        float s  = v.x + v.y + v.z + v.w;
        float sq = v.x*v.x + v.y*v.y + v.z*v.z + v.w*v.w;
        #pragma unroll
        for (int o = 16; o > 0; o >>= 1) {
            s  += __shfl_xor_sync(0xffffffffu, s,  o);
            sq += __shfl_xor_sync(0xffffffffu, sq, o);
        }
        float mu   = s * (1.0f / NDIM);
        float var  = sq * (1.0f / NDIM) - mu * mu;
        float rstd = rsqrtf(var + 1e-5f);
        if (n < NN) {
            float4 g  = reinterpret_cast<const float4*>(gamma)[lane];
            float4 be = reinterpret_cast<const float4*>(beta)[lane];
            float4 o;
            o.x = (v.x - mu) * rstd * g.x + be.x;
            o.y = (v.y - mu) * rstd * g.y + be.y;
            o.z = (v.z - mu) * rstd * g.z + be.z;
            o.w = (v.w - mu) * rstd * g.w + be.w;
            reinterpret_cast<float4*>(hout + (size_t)n * NDIM)[lane] = o;
        }
    }
}

extern "C" void kernel_launch(void* const* d_in, const int* in_sizes, int n_in,
                              void* d_out, int out_size)
{
    const float* h   = (const float*)d_in[0];
    const float* x   = (const float*)d_in[1];
    const int*   ei32 = (const int*)d_in[2];     // int32 OR int64 (probed at runtime)
    const float* ea  = (const float*)d_in[3];
    const float* mW1 = (const float*)d_in[4];
    const float* mb1 = (const float*)d_in[5];
    const float* mW2 = (const float*)d_in[6];
    const float* mb2 = (const float*)d_in[7];
    const float* nW1 = (const float*)d_in[8];
    const float* nb1 = (const float*)d_in[9];
    const float* nW2 = (const float*)d_in[10];
    const float* nb2 = (const float*)d_in[11];
    const float* cW1 = (const float*)d_in[12];
    const float* cb1 = (const float*)d_in[13];
    const float* cW2 = (const float*)d_in[14];
    const float* gamma = (const float*)d_in[15];
    const float* beta  = (const float*)d_in[16];

    float* hout = (float*)d_out;
    float* xout = hout + (size_t)NN * NDIM;
    long long E = (long long)in_sizes[2] / 2;    // element count / 2, dtype-independent

    const int edge_smem = (289*LDA + 256*LDA + 16*8 + TE*3 + TE) * 4;   // ~158.5 KB
    const int node_smem = ((NDIM+HDIM)*LDA + HDIM*LDA) * 4;             // ~184 KB
    cudaFuncSetAttribute(edge_kernel, cudaFuncAttributeMaxDynamicSharedMemorySize, edge_smem);
    cudaFuncSetAttribute(node_kernel, cudaFuncAttributeMaxDynamicSharedMemorySize, node_smem);

    {
        long long tot = (long long)NN * HDIM;
        int blocks = (int)((tot + 511) / 512);
        init_kernel<<<blocks, 512>>>(x, xout, ei32);
    }
    {
        int blocks = (int)((E + TE - 1) / TE);
        edge_kernel<<<blocks, 512, edge_smem>>>(h, x, ei32, ea, mW1, mb1, mW2, mb2,
                                                cW1, cb1, cW2, xout, E);
    }
    {
        int blocks = (NN + TN - 1) / TN;
        node_kernel<<<blocks, 512, node_smem>>>(h, nW1, nb1, nW2, nb2, gamma, beta, hout);
    }
}